// round 1
// baseline (speedup 1.0000x reference)
#include <cuda_runtime.h>
#include <math.h>
#include <stdint.h>

#define BB 16
#define QQ 1024
#define TT 1024
#define DD 256
#define EPS 0.1f
#define INV_EPS 10.0f
#define N_ITERS 5

// ---------------- device scratch (no allocations allowed) ----------------
__device__ float g_cost[(size_t)BB * QQ * TT];  // 64 MB cost matrix
__device__ float g_u[BB * QQ];
__device__ float g_v[BB * TT];
__device__ float g_x2[BB * QQ];
__device__ float g_y2[BB * TT];
__device__ unsigned int g_maxbits;              // global max(cost) as ordered uint

// ---------------- init ----------------
__global__ void init_kernel() {
    int i = blockIdx.x * blockDim.x + threadIdx.x;
    if (i == 0) g_maxbits = 0u;
    if (i < BB * QQ) g_u[i] = 0.0f;
    if (i < BB * TT) g_v[i] = 0.0f;
}

// ---------------- squared row norms: one warp per row ----------------
__global__ void norms_kernel(const float* __restrict__ preds,
                             const float* __restrict__ tgts) {
    int gwarp = (blockIdx.x * blockDim.x + threadIdx.x) >> 5;
    int lane = threadIdx.x & 31;
    const int NROWS = BB * QQ + BB * TT;
    if (gwarp >= NROWS) return;
    const float* src = (gwarp < BB * QQ)
                           ? preds + (size_t)gwarp * DD
                           : tgts + (size_t)(gwarp - BB * QQ) * DD;
    float s = 0.0f;
#pragma unroll
    for (int k = lane; k < DD; k += 32) {
        float x = src[k];
        s = fmaf(x, x, s);
    }
#pragma unroll
    for (int o = 16; o > 0; o >>= 1) s += __shfl_xor_sync(0xffffffffu, s, o);
    if (lane == 0) {
        if (gwarp < BB * QQ) g_x2[gwarp] = s;
        else g_y2[gwarp - BB * QQ] = s;
    }
}

// ---------------- cost = sqrt(max(x2+y2-2*A.B^T, 0)); track global max ----
// 128x128 tile, BK=8, 256 threads, 8x8 microtile per thread (fp32 FFMA GEMM).
__global__ void __launch_bounds__(256, 2)
cost_kernel(const float* __restrict__ preds, const float* __restrict__ tgts) {
    const int b = blockIdx.z;
    const int m_base = blockIdx.y * 128;
    const int n_base = blockIdx.x * 128;
    const float* Ag = preds + ((size_t)b * QQ + m_base) * DD;
    const float* Bg = tgts + ((size_t)b * TT + n_base) * DD;

    __shared__ float As[8][128];
    __shared__ float Bs[8][128];

    const int tid = threadIdx.x;
    const int lrow = tid >> 1;          // 0..127
    const int lcol = (tid & 1) << 2;    // 0 or 4
    const int tx = tid & 15;            // n microtile
    const int ty = tid >> 4;            // m microtile

    float acc[8][8] = {};

    for (int k0 = 0; k0 < DD; k0 += 8) {
        float4 av = *(const float4*)(Ag + (size_t)lrow * DD + k0 + lcol);
        float4 bv = *(const float4*)(Bg + (size_t)lrow * DD + k0 + lcol);
        As[lcol + 0][lrow] = av.x;
        As[lcol + 1][lrow] = av.y;
        As[lcol + 2][lrow] = av.z;
        As[lcol + 3][lrow] = av.w;
        Bs[lcol + 0][lrow] = bv.x;
        Bs[lcol + 1][lrow] = bv.y;
        Bs[lcol + 2][lrow] = bv.z;
        Bs[lcol + 3][lrow] = bv.w;
        __syncthreads();
#pragma unroll
        for (int kk = 0; kk < 8; kk++) {
            float ar[8], br[8];
            *(float4*)(&ar[0]) = *(const float4*)(&As[kk][ty * 8]);
            *(float4*)(&ar[4]) = *(const float4*)(&As[kk][ty * 8 + 4]);
            *(float4*)(&br[0]) = *(const float4*)(&Bs[kk][tx * 8]);
            *(float4*)(&br[4]) = *(const float4*)(&Bs[kk][tx * 8 + 4]);
#pragma unroll
            for (int i = 0; i < 8; i++)
#pragma unroll
                for (int j = 0; j < 8; j++)
                    acc[i][j] = fmaf(ar[i], br[j], acc[i][j]);
        }
        __syncthreads();
    }

    // epilogue: cost + max tracking + store
    float tmax = 0.0f;
#pragma unroll
    for (int i = 0; i < 8; i++) {
        float xi = g_x2[b * QQ + m_base + ty * 8 + i];
        float cbuf[8];
#pragma unroll
        for (int j = 0; j < 8; j++) {
            float yj = g_y2[b * TT + n_base + tx * 8 + j];
            float c2 = xi + yj - 2.0f * acc[i][j];
            float c = sqrtf(fmaxf(c2, 0.0f));
            cbuf[j] = c;
            tmax = fmaxf(tmax, c);
        }
        size_t off = ((size_t)(b * QQ + m_base + ty * 8 + i)) * TT + n_base + tx * 8;
        *(float4*)(g_cost + off) = make_float4(cbuf[0], cbuf[1], cbuf[2], cbuf[3]);
        *(float4*)(g_cost + off + 4) = make_float4(cbuf[4], cbuf[5], cbuf[6], cbuf[7]);
    }

    __shared__ unsigned int smax;
    if (tid == 0) smax = 0u;
    __syncthreads();
    atomicMax(&smax, __float_as_uint(tmax));  // costs are >= 0: uint order == float order
    __syncthreads();
    if (tid == 0) atomicMax(&g_maxbits, smax);
}

// ---------------- block reduction helpers (deterministic) ----------------
__device__ __forceinline__ float block_reduce_max(float v, float* sh8) {
#pragma unroll
    for (int o = 16; o > 0; o >>= 1) v = fmaxf(v, __shfl_xor_sync(0xffffffffu, v, o));
    int w = threadIdx.x >> 5;
    if ((threadIdx.x & 31) == 0) sh8[w] = v;
    __syncthreads();
    float r = sh8[0];
#pragma unroll
    for (int i = 1; i < 8; i++) r = fmaxf(r, sh8[i]);
    __syncthreads();
    return r;
}

__device__ __forceinline__ float block_reduce_sum(float v, float* sh8) {
#pragma unroll
    for (int o = 16; o > 0; o >>= 1) v += __shfl_xor_sync(0xffffffffu, v, o);
    int w = threadIdx.x >> 5;
    if ((threadIdx.x & 31) == 0) sh8[w] = v;
    __syncthreads();
    float r = sh8[0];
#pragma unroll
    for (int i = 1; i < 8; i++) r += sh8[i];
    __syncthreads();
    return r;
}

// ---------------- u update: one block per (b,q) row ----------------
__global__ void u_update(const float* __restrict__ filt) {
    const int row = blockIdx.x;       // b*QQ + q
    const int b = row >> 10;
    const float* crow = g_cost + (size_t)row * TT;
    const float* vb = g_v + b * TT;
    const float* fb = filt + b * TT;
    const float fc = 2.0f * __uint_as_float(g_maxbits);
    const int tid = threadIdx.x;

    __shared__ float sh8[8];

    float a[4];
    float m = -INFINITY;
#pragma unroll
    for (int i = 0; i < 4; i++) {
        int t = tid + i * 256;
        float c = crow[t];
        if (fb[t] <= 0.0f) c = fc;
        a[i] = (vb[t] - c) * INV_EPS;
        m = fmaxf(m, a[i]);
    }
    m = block_reduce_max(m, sh8);
    float s = 0.0f;
#pragma unroll
    for (int i = 0; i < 4; i++) s += expf(a[i] - m);
    s = block_reduce_sum(s, sh8);
    if (tid == 0) g_u[row] = -EPS * (logf(s) + m);
}

// ---------------- v update: one block per (b, 32-t strip) ----------------
// blockDim = (32, 8). lane -> t; wy strides over q. Online logsumexp.
__global__ void v_update(const float* __restrict__ filt) {
    const int b = blockIdx.y;
    const int t = blockIdx.x * 32 + threadIdx.x;
    const int wy = threadIdx.y;
    const float fc = 2.0f * __uint_as_float(g_maxbits);
    const bool filtered = (filt[b * TT + t] <= 0.0f);
    const float* base = g_cost + ((size_t)b * QQ) * TT + t;
    const float* ub = g_u + b * QQ;

    float m = -INFINITY, s = 0.0f;
    for (int q0 = wy; q0 < QQ; q0 += 32) {
        // 4 loads in flight (q0, q0+8, q0+16, q0+24)
        float c0 = base[(size_t)(q0 + 0) * TT];
        float c1 = base[(size_t)(q0 + 8) * TT];
        float c2 = base[(size_t)(q0 + 16) * TT];
        float c3 = base[(size_t)(q0 + 24) * TT];
        float u0 = ub[q0 + 0], u1 = ub[q0 + 8], u2 = ub[q0 + 16], u3 = ub[q0 + 24];
        if (filtered) { c0 = fc; c1 = fc; c2 = fc; c3 = fc; }
        float a0 = (u0 - c0) * INV_EPS;
        float a1 = (u1 - c1) * INV_EPS;
        float a2 = (u2 - c2) * INV_EPS;
        float a3 = (u3 - c3) * INV_EPS;
#pragma unroll
        for (int k = 0; k < 4; k++) {
            float a = (k == 0) ? a0 : (k == 1) ? a1 : (k == 2) ? a2 : a3;
            if (a > m) { s = s * expf(m - a) + 1.0f; m = a; }
            else       { s += expf(a - m); }
        }
    }

    __shared__ float sm[8][32];
    __shared__ float ss[8][32];
    sm[wy][threadIdx.x] = m;
    ss[wy][threadIdx.x] = s;
    __syncthreads();
    if (wy == 0) {
        float M = m, S = s;
#pragma unroll
        for (int w = 1; w < 8; w++) {
            float m2 = sm[w][threadIdx.x];
            float s2 = ss[w][threadIdx.x];
            if (m2 > M) { S = S * expf(M - m2) + s2; M = m2; }
            else        { S += s2 * expf(m2 - M); }
        }
        g_v[b * TT + t] = -EPS * (logf(S) + M);
    }
}

// ---------------- final: P = exp((u+v-c)/eps), argmax_t (first max) ------
__global__ void p_argmax_kernel(const float* __restrict__ filt,
                                float* __restrict__ outP,
                                float* __restrict__ outIdx) {
    const int row = blockIdx.x;       // b*QQ + q
    const int b = row >> 10;
    const float* crow = g_cost + (size_t)row * TT;
    const float* vb = g_v + b * TT;
    const float* fb = filt + b * TT;
    const float fc = 2.0f * __uint_as_float(g_maxbits);
    const float u = g_u[row];
    const int tid = threadIdx.x;

    float bestv = -INFINITY;
    int besti = 0x7fffffff;
#pragma unroll
    for (int i = 0; i < 4; i++) {
        int t = tid + i * 256;
        float c = crow[t];
        if (fb[t] <= 0.0f) c = fc;
        float p = expf((u + vb[t] - c) * INV_EPS);
        if (outP) outP[(size_t)row * TT + t] = p;
        if (p > bestv) { bestv = p; besti = t; }   // ascending t per thread -> first max kept
    }

    __shared__ float sv[256];
    __shared__ int si[256];
    sv[tid] = bestv;
    si[tid] = besti;
    __syncthreads();
#pragma unroll
    for (int st = 128; st > 0; st >>= 1) {
        if (tid < st) {
            float v2 = sv[tid + st];
            int i2 = si[tid + st];
            if (v2 > sv[tid] || (v2 == sv[tid] && i2 < si[tid])) {
                sv[tid] = v2;
                si[tid] = i2;
            }
        }
        __syncthreads();
    }
    if (tid == 0 && outIdx) outIdx[row] = (float)si[0];
}

// ---------------- launch ----------------
extern "C" void kernel_launch(void* const* d_in, const int* in_sizes, int n_in,
                              void* d_out, int out_size) {
    const float* preds = (const float*)d_in[0];
    const float* tgts = (const float*)d_in[1];
    const float* filt = (const float*)d_in[2];
    float* out = (float*)d_out;

    const int NP = BB * QQ * TT;
    const int NI = BB * QQ;
    float* outIdx = nullptr;
    float* outP = nullptr;
    if (out_size == NP + NI) { outIdx = out; outP = out + NI; }
    else if (out_size == NP) { outP = out; }
    else if (out_size == NI) { outIdx = out; }
    else { outIdx = out; outP = out + NI; }  // best guess

    init_kernel<<<(BB * QQ + 255) / 256, 256>>>();
    {
        const int nwarps = BB * QQ + BB * TT;  // 32768 rows, one warp each
        norms_kernel<<<(nwarps * 32 + 255) / 256, 256>>>(preds, tgts);
    }
    cost_kernel<<<dim3(TT / 128, QQ / 128, BB), 256>>>(preds, tgts);
    for (int it = 0; it < N_ITERS; it++) {
        u_update<<<BB * QQ, 256>>>(filt);
        v_update<<<dim3(TT / 32, BB), dim3(32, 8)>>>(filt);
    }
    p_argmax_kernel<<<BB * QQ, 256>>>(filt, outP, outIdx);
}